// round 16
// baseline (speedup 1.0000x reference)
#include <cuda_runtime.h>
#include <cuda_bf16.h>
#include <cuda_fp16.h>
#include <math.h>
#include <stdint.h>

#define NN 50000
#define EE 800000
#define CAP 64
#define SBLK 196  // ceil(50000/256)

// ================= scratch ==================================================
struct GS {
    float skb[(size_t)NN * 256];
    __half agg0f[(size_t)NN * 256];
    __half agg1f[(size_t)NN * 256];
    float h2fw[(size_t)NN * 128];
    __half h0f[(size_t)NN * 256];
    __half h1f[(size_t)NN * 256];
    __half h2f[(size_t)NN * 64];
    float as0[NN * 8], ad0[NN * 8], as1[NN * 8], ad1[NN * 8];
    float as2[NN], ad2[NN];
    __half xf[(size_t)NN * 256];
    __nv_bfloat16 fxh[(size_t)NN * 256], fxl[(size_t)NN * 256];
    __half B1f[768 * 256];
    __nv_bfloat16 B2h[128 * 256], B2l[128 * 256];
    int deg0[NN], deg1[NN];
    int off0[NN + 1], off1[NN + 1];
    int cur0[NN], cur1[NN];
    int bsum[2 * SBLK];
    int csr0[EE], csr1[EE];
};
__device__ GS gs;

// ================= helpers ==================================================
__device__ __forceinline__ float wredsum(float v) {
#pragma unroll
    for (int o = 16; o; o >>= 1) v += __shfl_xor_sync(0xffffffffu, v, o);
    return v;
}
__device__ __forceinline__ float wredmax(float v) {
#pragma unroll
    for (int o = 16; o; o >>= 1) v = fmaxf(v, __shfl_xor_sync(0xffffffffu, v, o));
    return v;
}
__device__ __forceinline__ int wscan_incl(int v, int lane) {
#pragma unroll
    for (int o = 1; o < 32; o <<= 1) {
        int t = __shfl_up_sync(0xffffffffu, v, o);
        if (lane >= o) v += t;
    }
    return v;
}
__device__ __forceinline__ float lrelu(float x) { return fmaxf(x, 0.2f * x); }
__device__ __forceinline__ uint32_t smem_u32(const void* p) {
    uint32_t a;
    asm("{ .reg .u64 t; cvta.to.shared.u64 t, %1; cvt.u32.u64 %0, t; }" : "=r"(a) : "l"(p));
    return a;
}
__device__ __forceinline__ void cp16(uint32_t dst, const void* src, bool v) {
    int bytes = v ? 16 : 0;
    asm volatile("cp.async.cg.shared.global [%0], [%1], 16, %2;\n"
                 :: "r"(dst), "l"(src), "r"(bytes));
}
__device__ __forceinline__ void ldsm4(uint32_t* r, uint32_t addr) {
    asm volatile("ldmatrix.sync.aligned.m8n8.x4.shared.b16 {%0,%1,%2,%3}, [%4];\n"
                 : "=r"(r[0]), "=r"(r[1]), "=r"(r[2]), "=r"(r[3]) : "r"(addr));
}
__device__ __forceinline__ void mma_bf16(float* d, const uint32_t* a, uint32_t b0, uint32_t b1) {
    asm volatile(
        "mma.sync.aligned.m16n8k16.row.col.f32.bf16.bf16.f32 "
        "{%0,%1,%2,%3}, {%4,%5,%6,%7}, {%8,%9}, {%0,%1,%2,%3};\n"
        : "+f"(d[0]), "+f"(d[1]), "+f"(d[2]), "+f"(d[3])
        : "r"(a[0]), "r"(a[1]), "r"(a[2]), "r"(a[3]), "r"(b0), "r"(b1));
}
__device__ __forceinline__ void mma_f16(float* d, const uint32_t* a, uint32_t b0, uint32_t b1) {
    asm volatile(
        "mma.sync.aligned.m16n8k16.row.col.f32.f16.f16.f32 "
        "{%0,%1,%2,%3}, {%4,%5,%6,%7}, {%8,%9}, {%0,%1,%2,%3};\n"
        : "+f"(d[0]), "+f"(d[1]), "+f"(d[2]), "+f"(d[3])
        : "r"(a[0]), "r"(a[1]), "r"(a[2]), "r"(a[3]), "r"(b0), "r"(b1));
}
__device__ __forceinline__ void fma8(float2* acc, uint4 r, float a) {
    float2 x0 = __half22float2(*(__half2*)&r.x);
    float2 x1 = __half22float2(*(__half2*)&r.y);
    float2 x2 = __half22float2(*(__half2*)&r.z);
    float2 x3 = __half22float2(*(__half2*)&r.w);
    acc[0].x += a * x0.x; acc[0].y += a * x0.y;
    acc[1].x += a * x1.x; acc[1].y += a * x1.y;
    acc[2].x += a * x2.x; acc[2].y += a * x2.y;
    acc[3].x += a * x3.x; acc[3].y += a * x3.y;
}

// ================= CSR build ================================================
__global__ void zero_int(int* p, int n) {
    int i = blockIdx.x * blockDim.x + threadIdx.x;
    if (i < n) p[i] = 0;
}
__global__ void hist2(const int* __restrict__ d0, const int* __restrict__ d1,
                      int* __restrict__ deg0, int* __restrict__ deg1) {
    int i = blockIdx.x * blockDim.x + threadIdx.x;
    if (i < EE) atomicAdd(&deg0[d0[i]], 1);
    else if (i < 2 * EE) atomicAdd(&deg1[d1[i - EE]], 1);
}
__global__ void scan_part(const int* __restrict__ deg0, const int* __restrict__ deg1,
                          int* __restrict__ bsum) {
    __shared__ int wsum[8];
    const int* deg = blockIdx.y ? deg1 : deg0;
    int tid = threadIdx.x, lane = tid & 31, warp = tid >> 5;
    int i = blockIdx.x * 256 + tid;
    int v = (i < NN) ? deg[i] : 0;
#pragma unroll
    for (int o = 16; o; o >>= 1) v += __shfl_xor_sync(0xffffffffu, v, o);
    if (lane == 0) wsum[warp] = v;
    __syncthreads();
    if (tid == 0) {
        int t = 0;
#pragma unroll
        for (int w = 0; w < 8; w++) t += wsum[w];
        bsum[blockIdx.y * SBLK + blockIdx.x] = t;
    }
}
__global__ void scan_mid(int* __restrict__ bsum, int* __restrict__ off0, int* __restrict__ off1) {
    __shared__ int wpre[8];
    int g = blockIdx.x;
    int tid = threadIdx.x, lane = tid & 31, warp = tid >> 5;
    int v = (tid < SBLK) ? bsum[g * SBLK + tid] : 0;
    int incl = wscan_incl(v, lane);
    if (lane == 31) wpre[warp] = incl;
    __syncthreads();
    if (warp == 0) {
        int w = (lane < 8) ? wpre[lane] : 0;
        int wi = wscan_incl(w, lane);
        if (lane < 8) wpre[lane] = wi - w;
    }
    __syncthreads();
    int excl = wpre[warp] + incl - v;
    if (tid < SBLK) bsum[g * SBLK + tid] = excl;
    if (tid == SBLK - 1) {
        int total = excl + v;
        if (g == 0) off0[NN] = total; else off1[NN] = total;
    }
}
__global__ void scan_emit(const int* __restrict__ deg0, const int* __restrict__ deg1,
                          const int* __restrict__ bsum,
                          int* __restrict__ off0, int* __restrict__ cur0,
                          int* __restrict__ off1, int* __restrict__ cur1) {
    __shared__ int wpre[8];
    int g = blockIdx.y;
    const int* deg = g ? deg1 : deg0;
    int* off = g ? off1 : off0;
    int* cur = g ? cur1 : cur0;
    int tid = threadIdx.x, lane = tid & 31, warp = tid >> 5;
    int i = blockIdx.x * 256 + tid;
    int v = (i < NN) ? deg[i] : 0;
    int incl = wscan_incl(v, lane);
    if (lane == 31) wpre[warp] = incl;
    __syncthreads();
    if (warp == 0) {
        int w = (lane < 8) ? wpre[lane] : 0;
        int wi = wscan_incl(w, lane);
        if (lane < 8) wpre[lane] = wi - w;
    }
    __syncthreads();
    int excl = bsum[g * SBLK + blockIdx.x] + wpre[warp] + incl - v;
    if (i < NN) {
        off[i] = excl;
        cur[i] = excl;
    }
}
__global__ void scatter2(const int* __restrict__ e0, const int* __restrict__ e1,
                         int* __restrict__ cur0, int* __restrict__ cur1,
                         int* __restrict__ csr0, int* __restrict__ csr1) {
    int i = blockIdx.x * blockDim.x + threadIdx.x;
    if (i < EE) {
        int d = e0[EE + i];
        int p = atomicAdd(&cur0[d], 1);
        csr0[p] = e0[i];
    } else if (i < 2 * EE) {
        int j = i - EE;
        int d = e1[EE + j];
        int p = atomicAdd(&cur1[d], 1);
        csr1[p] = e1[j];
    }
}

// ================= operand packing ==========================================
__global__ void split_x(const float* __restrict__ x, __half* __restrict__ xf, int n) {
    int i = blockIdx.x * blockDim.x + threadIdx.x;
    if (i < n) xf[i] = __float2half_rn(x[i]);
}
__global__ void pack_B1f(const float* __restrict__ W1, const float* __restrict__ skipW,
                         __half* __restrict__ Bf) {
    int i = blockIdx.x * blockDim.x + threadIdx.x;
    if (i >= 768 * 256) return;
    int n = i / 256, k = i % 256;
    float v;
    if (n < 256) v = W1[k * 256 + n];
    else if (n < 512) v = W1[65536 + k * 256 + (n - 256)];
    else v = skipW[k * 256 + (n - 512)];
    Bf[i] = __float2half_rn(v);
}
__global__ void pack_B2(const float* __restrict__ W2, const float* __restrict__ finalW,
                        __nv_bfloat16* __restrict__ Bh, __nv_bfloat16* __restrict__ Bl) {
    int i = blockIdx.x * blockDim.x + threadIdx.x;
    if (i >= 128 * 256) return;
    int n = i / 256, k = i % 256;
    float v = (n < 64) ? W2[k * 64 + n] : finalW[k * 64 + (n - 64)];
    __nv_bfloat16 h = __float2bfloat16(v);
    Bh[i] = h;
    Bl[i] = __float2bfloat16(v - __bfloat162float(h));
}

// ====== fp16 single-pass HMMA GEMM: A[M,256] @ B[768,256]^T =================
__global__ __launch_bounds__(256, 2) void hmma_gemm_f16(
    const __half* __restrict__ A, const __half* __restrict__ B,
    __half* __restrict__ H0, __half* __restrict__ H1, float* __restrict__ C2, int M) {
    extern __shared__ char sm[];
    const int tid = threadIdx.x, lane = tid & 31, warp = tid >> 5;
    const int wm = warp & 1, wn = warp >> 1;
    const int m0 = blockIdx.y * 128, n0 = blockIdx.x * 128;
    uint32_t sbase = smem_u32(sm);

    float acc[4][4][4];
#pragma unroll
    for (int a = 0; a < 4; a++)
#pragma unroll
        for (int b = 0; b < 4; b++)
#pragma unroll
            for (int q = 0; q < 4; q++) acc[a][b][q] = 0.f;

#define LOADF(c, s)                                                               \
    do {                                                                          \
        uint32_t sb_ = sbase + (s) * 20480;                                       \
        _Pragma("unroll") for (int it = 0; it < 2; it++) {                        \
            int idx = tid + it * 256;                                             \
            int row = idx >> 2, kc = idx & 3;                                     \
            uint32_t so = row * 80 + kc * 16;                                     \
            bool va = (m0 + row) < M;                                             \
            long ga = (long)(m0 + row) * 256 + (c) * 32 + kc * 8;                 \
            if (!va) ga = 0;                                                      \
            cp16(sb_ + so, A + ga, va);                                           \
            long gb = (long)(n0 + row) * 256 + (c) * 32 + kc * 8;                 \
            cp16(sb_ + 10240 + so, B + gb, true);                                 \
        }                                                                         \
        asm volatile("cp.async.commit_group;\n" ::: "memory");                    \
    } while (0)

    LOADF(0, 0);
    LOADF(1, 1);
    for (int c = 0; c < 8; c++) {
        if (c + 2 < 8) LOADF(c + 2, (c + 2) % 3);
        if (c < 6) asm volatile("cp.async.wait_group 2;\n" ::: "memory");
        else if (c == 6) asm volatile("cp.async.wait_group 1;\n" ::: "memory");
        else asm volatile("cp.async.wait_group 0;\n" ::: "memory");
        __syncthreads();
        uint32_t sb = sbase + (c % 3) * 20480;
#pragma unroll
        for (int ks = 0; ks < 2; ks++) {
            uint32_t ah[4][4], bh[2][4];
            int acol = ks * 16 + 8 * (lane >> 4);
            int arowl = (lane & 15);
#pragma unroll
            for (int mf = 0; mf < 4; mf++) {
                int arow = wm * 64 + mf * 16 + arowl;
                ldsm4(ah[mf], sb + arow * 80 + acol * 2);
            }
            int bcol = ks * 16 + 8 * ((lane >> 3) & 1);
            int browl = (lane & 7) + 8 * (lane >> 4);
#pragma unroll
            for (int p = 0; p < 2; p++) {
                int brow = wn * 32 + p * 16 + browl;
                ldsm4(bh[p], sb + 10240 + brow * 80 + bcol * 2);
            }
#pragma unroll
            for (int mf = 0; mf < 4; mf++)
#pragma unroll
                for (int p = 0; p < 2; p++)
#pragma unroll
                    for (int sub = 0; sub < 2; sub++) {
                        int nf = p * 2 + sub;
                        mma_f16(acc[mf][nf], ah[mf], bh[p][sub * 2], bh[p][sub * 2 + 1]);
                    }
        }
        __syncthreads();
    }
#undef LOADF

    int bucket = n0 >> 8;
    int cb = n0 & 255;
    int group = lane >> 2, q = lane & 3;
    if (bucket < 2) {
        __half2* H = (__half2*)((bucket == 0) ? H0 : H1);
#pragma unroll
        for (int mf = 0; mf < 4; mf++) {
            int r0 = m0 + wm * 64 + mf * 16 + group;
#pragma unroll
            for (int nf = 0; nf < 4; nf++) {
                int col = cb + wn * 32 + nf * 8 + q * 2;
                if (r0 < M)
                    H[(long)r0 * 128 + col / 2] =
                        __floats2half2_rn(acc[mf][nf][0], acc[mf][nf][1]);
                if (r0 + 8 < M)
                    H[(long)(r0 + 8) * 128 + col / 2] =
                        __floats2half2_rn(acc[mf][nf][2], acc[mf][nf][3]);
            }
        }
    } else {
#pragma unroll
        for (int mf = 0; mf < 4; mf++) {
            int r0 = m0 + wm * 64 + mf * 16 + group;
#pragma unroll
            for (int nf = 0; nf < 4; nf++) {
                int col = cb + wn * 32 + nf * 8 + q * 2;
                if (r0 < M)
                    *(float2*)(C2 + (long)r0 * 256 + col) =
                        make_float2(acc[mf][nf][0], acc[mf][nf][1]);
                if (r0 + 8 < M)
                    *(float2*)(C2 + (long)(r0 + 8) * 256 + col) =
                        make_float2(acc[mf][nf][2], acc[mf][nf][3]);
            }
        }
    }
}

// ====== bf16-split HMMA GEMM (3 MMA): fp32 out + fp16 mirror cols<64 ========
__global__ __launch_bounds__(256, 2) void hmma_gemm(
    const __nv_bfloat16* __restrict__ Ah, const __nv_bfloat16* __restrict__ Al,
    const __nv_bfloat16* __restrict__ Bh, const __nv_bfloat16* __restrict__ Bl,
    float* __restrict__ C, __half* __restrict__ Hf, int M, int split) {
    extern __shared__ char sm[];
    const int tid = threadIdx.x, lane = tid & 31, warp = tid >> 5;
    const int wm = warp & 1, wn = warp >> 1;
    const int m0 = blockIdx.y * 128, n0 = blockIdx.x * 128;
    uint32_t sbase = smem_u32(sm);

    float acc[4][4][4];
#pragma unroll
    for (int a = 0; a < 4; a++)
#pragma unroll
        for (int b = 0; b < 4; b++)
#pragma unroll
            for (int q = 0; q < 4; q++) acc[a][b][q] = 0.f;

#define LOAD_STAGE(c, s)                                                          \
    do {                                                                          \
        uint32_t sb_ = sbase + (s) * 40960;                                       \
        _Pragma("unroll") for (int it = 0; it < 2; it++) {                        \
            int idx = tid + it * 256;                                             \
            int row = idx >> 2, kc = idx & 3;                                     \
            uint32_t so = row * 80 + kc * 16;                                     \
            bool va = (m0 + row) < M;                                             \
            long ga = (long)(m0 + row) * 256 + (c) * 32 + kc * 8;                 \
            if (!va) ga = 0;                                                      \
            cp16(sb_ + so, Ah + ga, va);                                          \
            cp16(sb_ + 10240 + so, Al + ga, va);                                  \
            long gb = (long)(n0 + row) * 256 + (c) * 32 + kc * 8;                 \
            cp16(sb_ + 20480 + so, Bh + gb, true);                                \
            cp16(sb_ + 30720 + so, Bl + gb, true);                                \
        }                                                                         \
        asm volatile("cp.async.commit_group;\n" ::: "memory");                    \
    } while (0)

    LOAD_STAGE(0, 0);
    for (int c = 0; c < 8; c++) {
        if (c < 7) {
            LOAD_STAGE(c + 1, (c + 1) & 1);
            asm volatile("cp.async.wait_group 1;\n" ::: "memory");
        } else {
            asm volatile("cp.async.wait_group 0;\n" ::: "memory");
        }
        __syncthreads();
        uint32_t sb = sbase + (c & 1) * 40960;
#pragma unroll
        for (int ks = 0; ks < 2; ks++) {
            uint32_t ah[4][4], al[4][4], bhf[2][4], blf[2][4];
            int acol = ks * 16 + 8 * (lane >> 4);
            int arowl = (lane & 15);
#pragma unroll
            for (int mf = 0; mf < 4; mf++) {
                int arow = wm * 64 + mf * 16 + arowl;
                uint32_t ad = sb + arow * 80 + acol * 2;
                ldsm4(ah[mf], ad);
                ldsm4(al[mf], ad + 10240);
            }
            int bcol = ks * 16 + 8 * ((lane >> 3) & 1);
            int browl = (lane & 7) + 8 * (lane >> 4);
#pragma unroll
            for (int p = 0; p < 2; p++) {
                int brow = wn * 32 + p * 16 + browl;
                uint32_t bd = sb + 20480 + brow * 80 + bcol * 2;
                ldsm4(bhf[p], bd);
                ldsm4(blf[p], bd + 10240);
            }
#pragma unroll
            for (int mf = 0; mf < 4; mf++)
#pragma unroll
                for (int p = 0; p < 2; p++)
#pragma unroll
                    for (int sub = 0; sub < 2; sub++) {
                        int nf = p * 2 + sub;
                        uint32_t h0 = bhf[p][sub * 2], h1 = bhf[p][sub * 2 + 1];
                        uint32_t l0 = blf[p][sub * 2], l1 = blf[p][sub * 2 + 1];
                        mma_bf16(acc[mf][nf], ah[mf], h0, h1);
                        mma_bf16(acc[mf][nf], ah[mf], l0, l1);
                        mma_bf16(acc[mf][nf], al[mf], h0, h1);
                    }
        }
        __syncthreads();
    }
#undef LOAD_STAGE

    int cb = n0 % split;
    int group = lane >> 2, q = lane & 3;
#pragma unroll
    for (int mf = 0; mf < 4; mf++) {
        int r0 = m0 + wm * 64 + mf * 16 + group;
#pragma unroll
        for (int nf = 0; nf < 4; nf++) {
            int col = cb + wn * 32 + nf * 8 + q * 2;
            bool lo = (col < 64) && Hf;
            if (r0 < M) {
                if (lo)
                    ((__half2*)Hf)[(long)r0 * 32 + col / 2] =
                        __floats2half2_rn(acc[mf][nf][0], acc[mf][nf][1]);
                *(float2*)(C + (long)r0 * split + col) =
                    make_float2(acc[mf][nf][0], acc[mf][nf][1]);
            }
            if (r0 + 8 < M) {
                if (lo)
                    ((__half2*)Hf)[(long)(r0 + 8) * 32 + col / 2] =
                        __floats2half2_rn(acc[mf][nf][2], acc[mf][nf][3]);
                *(float2*)(C + (long)(r0 + 8) * split + col) =
                    make_float2(acc[mf][nf][2], acc[mf][nf][3]);
            }
        }
    }
}

// ================= attention logits (both hops in one launch) ===============
__global__ void logits8_2(const __half2* __restrict__ h0, const __half2* __restrict__ h1,
                          const float* __restrict__ a_src, const float* __restrict__ a_dst,
                          float* __restrict__ as0, float* __restrict__ ad0,
                          float* __restrict__ as1, float* __restrict__ ad1) {
    int t = blockIdx.x * blockDim.x + threadIdx.x;
    if (t >= NN * 8) return;
    int hop = blockIdx.y;
    const __half2* h = hop ? h1 : h0;
    float* as = hop ? as1 : as0;
    float* ad = hop ? ad1 : ad0;
    int v = t >> 3, k = t & 7;
    const __half2* hr = h + (long)v * 128 + k * 16;
    const float* sv = a_src + hop * 256 + k * 32;
    const float* dv = a_dst + hop * 256 + k * 32;
    float s = 0.f, d = 0.f;
#pragma unroll
    for (int c = 0; c < 16; c++) {
        float2 hv = __half22float2(hr[c]);
        s += hv.x * sv[2 * c] + hv.y * sv[2 * c + 1];
        d += hv.x * dv[2 * c] + hv.y * dv[2 * c + 1];
    }
    as[t] = s;
    ad[t] = d;
}
__global__ void logits1(const __half2* __restrict__ h2, const float* __restrict__ a_src,
                        const float* __restrict__ a_dst, float* __restrict__ as,
                        float* __restrict__ ad) {
    int v = blockIdx.x * blockDim.x + threadIdx.x;
    if (v >= NN) return;
    const __half2* hr = h2 + (long)v * 32;
    float s = 0.f, d = 0.f;
#pragma unroll
    for (int c = 0; c < 32; c++) {
        float2 hv = __half22float2(hr[c]);
        s += hv.x * a_src[2 * c] + hv.y * a_src[2 * c + 1];
        d += hv.x * a_dst[2 * c] + hv.y * a_dst[2 * c + 1];
    }
    as[v] = s;
    ad[v] = d;
}

// ====== GAT aggregation: both hops, warp/dst, fp16 agg output ===============
__global__ __launch_bounds__(256) void gat_agg8_2(
    const __half* __restrict__ h0p, const __half* __restrict__ h1p,
    const float* __restrict__ as0, const float* __restrict__ ad0,
    const float* __restrict__ as1, const float* __restrict__ ad1,
    const int* __restrict__ off0, const int* __restrict__ csr0,
    const int* __restrict__ off1, const int* __restrict__ csr1,
    __half* __restrict__ agg0, __half* __restrict__ agg1) {
    __shared__ float sal[8][CAP * 9];
    int gwarp = (blockIdx.x * blockDim.x + threadIdx.x) >> 5;
    int lane = threadIdx.x & 31;
    if (gwarp >= NN) return;
    int hop = blockIdx.y;
    const __half* h = hop ? h1p : h0p;
    const float* as = hop ? as1 : as0;
    const float* ad = hop ? ad1 : ad0;
    const int* off = hop ? off1 : off0;
    const int* csr = hop ? csr1 : csr0;
    __half* out = hop ? agg1 : agg0;

    int v = gwarp;
    float* sm = sal[threadIdx.x >> 5];
    int s0 = off[v], d = off[v + 1] - s0;
    int head = lane >> 2;

    float adv[8], asv[8];
    {
        float4 a0 = *(const float4*)(ad + v * 8);
        float4 a1 = *(const float4*)(ad + v * 8 + 4);
        adv[0] = a0.x; adv[1] = a0.y; adv[2] = a0.z; adv[3] = a0.w;
        adv[4] = a1.x; adv[5] = a1.y; adv[6] = a1.z; adv[7] = a1.w;
        float4 b0 = *(const float4*)(as + v * 8);
        float4 b1 = *(const float4*)(as + v * 8 + 4);
        asv[0] = b0.x; asv[1] = b0.y; asv[2] = b0.z; asv[3] = b0.w;
        asv[4] = b1.x; asv[5] = b1.y; asv[6] = b1.z; asv[7] = b1.w;
    }
    float m[8], den[8];
#pragma unroll
    for (int k = 0; k < 8; k++) m[k] = lrelu(asv[k] + adv[k]);

    bool fits = (d <= CAP);
    if (fits) {
        for (int j = lane; j < d; j += 32) {
            int s = csr[s0 + j];
            float4 a0 = *(const float4*)(as + s * 8);
            float4 a1 = *(const float4*)(as + s * 8 + 4);
            float ev[8] = {a0.x, a0.y, a0.z, a0.w, a1.x, a1.y, a1.z, a1.w};
#pragma unroll
            for (int k = 0; k < 8; k++) {
                float e = lrelu(ev[k] + adv[k]);
                sm[j * 9 + k] = e;
                m[k] = fmaxf(m[k], e);
            }
        }
#pragma unroll
        for (int k = 0; k < 8; k++) m[k] = wredmax(m[k]);
#pragma unroll
        for (int k = 0; k < 8; k++)
            den[k] = (lane == 0) ? __expf(lrelu(asv[k] + adv[k]) - m[k]) : 0.f;
        for (int j = lane; j < d; j += 32) {
#pragma unroll
            for (int k = 0; k < 8; k++) {
                float e = __expf(sm[j * 9 + k] - m[k]);
                sm[j * 9 + k] = e;
                den[k] += e;
            }
        }
#pragma unroll
        for (int k = 0; k < 8; k++) {
            den[k] = wredsum(den[k]);
            den[k] = 1.f / (den[k] + 1e-16f);
        }
        __syncwarp();
    } else {
        for (int j = lane; j < d; j += 32) {
            int s = csr[s0 + j];
#pragma unroll
            for (int k = 0; k < 8; k++) m[k] = fmaxf(m[k], lrelu(as[s * 8 + k] + adv[k]));
        }
#pragma unroll
        for (int k = 0; k < 8; k++) m[k] = wredmax(m[k]);
#pragma unroll
        for (int k = 0; k < 8; k++)
            den[k] = (lane == 0) ? __expf(lrelu(asv[k] + adv[k]) - m[k]) : 0.f;
        for (int j = lane; j < d; j += 32) {
            int s = csr[s0 + j];
#pragma unroll
            for (int k = 0; k < 8; k++)
                den[k] += __expf(lrelu(as[s * 8 + k] + adv[k]) - m[k]);
        }
#pragma unroll
        for (int k = 0; k < 8; k++) {
            den[k] = wredsum(den[k]);
            den[k] = 1.f / (den[k] + 1e-16f);
        }
    }

    float msel = m[0], dsel = den[0], advsel = adv[0], slsel = asv[0] + adv[0];
#pragma unroll
    for (int k = 1; k < 8; k++)
        if (head == k) { msel = m[k]; dsel = den[k]; advsel = adv[k]; slsel = asv[k] + adv[k]; }
    float esel = __expf(lrelu(slsel) - msel) * dsel;

    float2 acc[4];
    {
        uint4 r = *((const uint4*)(h + (long)v * 256) + lane);
        acc[0] = acc[1] = acc[2] = acc[3] = make_float2(0.f, 0.f);
        fma8(acc, r, esel);
    }
    if (fits) {
        int j = 0;
        for (; j + 8 <= d; j += 8) {
            int sx[8];
#pragma unroll
            for (int u = 0; u < 8; u++) sx[u] = csr[s0 + j + u];
            uint4 r[8];
#pragma unroll
            for (int u = 0; u < 8; u++)
                r[u] = *((const uint4*)(h + (long)sx[u] * 256) + lane);
#pragma unroll
            for (int u = 0; u < 8; u++) fma8(acc, r[u], sm[(j + u) * 9 + head] * dsel);
        }
        for (; j + 4 <= d; j += 4) {
            int sx[4];
#pragma unroll
            for (int u = 0; u < 4; u++) sx[u] = csr[s0 + j + u];
            uint4 r[4];
#pragma unroll
            for (int u = 0; u < 4; u++)
                r[u] = *((const uint4*)(h + (long)sx[u] * 256) + lane);
#pragma unroll
            for (int u = 0; u < 4; u++) fma8(acc, r[u], sm[(j + u) * 9 + head] * dsel);
        }
        for (; j < d; j++) {
            int s = csr[s0 + j];
            uint4 r = *((const uint4*)(h + (long)s * 256) + lane);
            fma8(acc, r, sm[j * 9 + head] * dsel);
        }
    } else {
        for (int j = 0; j < d; j++) {
            int s = csr[s0 + j];
            uint4 r = *((const uint4*)(h + (long)s * 256) + lane);
            float a = __expf(lrelu(as[s * 8 + head] + advsel) - msel) * dsel;
            fma8(acc, r, a);
        }
    }
    // fp16 output: 8 halves = one 16B store per lane
    __half2 oh[4];
#pragma unroll
    for (int k = 0; k < 4; k++) oh[k] = __floats2half2_rn(acc[k].x, acc[k].y);
    *((uint4*)(out + (long)v * 256 + lane * 8)) = *(uint4*)oh;
}

// ========== hop combine + skip + LN1 (fp16 agg in, lane*8 layout) ===========
__global__ __launch_bounds__(256) void combine_ln(const __half* __restrict__ agg0,
                                                  const __half* __restrict__ agg1,
                                                  const float* __restrict__ skb,
                                                  const float* __restrict__ b1,
                                                  const float* __restrict__ skip_b,
                                                  const float* __restrict__ ha,
                                                  const float* __restrict__ g,
                                                  const float* __restrict__ bt,
                                                  __nv_bfloat16* __restrict__ fxh,
                                                  __nv_bfloat16* __restrict__ fxl) {
    int warp = (blockIdx.x * blockDim.x + threadIdx.x) >> 5;
    int lane = threadIdx.x & 31;
    if (warp >= NN) return;
    int v = warp;
    float a0h = ha[0], a1h = ha[1];
    float mx = fmaxf(a0h, a1h);
    float e0 = __expf(a0h - mx), e1 = __expf(a1h - mx);
    float winv = 1.f / (e0 + e1);
    float w0 = e0 * winv, w1 = e1 * winv;

    int cbase = lane * 8;
    uint4 a0r = *((const uint4*)(agg0 + (long)v * 256 + cbase));
    uint4 a1r = *((const uint4*)(agg1 + (long)v * 256 + cbase));
    const __half* a0p = (const __half*)&a0r;
    const __half* a1p = (const __half*)&a1r;
    float4 sk0 = *(const float4*)(skb + (long)v * 256 + cbase);
    float4 sk1 = *(const float4*)(skb + (long)v * 256 + cbase + 4);
    float skv[8] = {sk0.x, sk0.y, sk0.z, sk0.w, sk1.x, sk1.y, sk1.z, sk1.w};

    float vals[8];
    float lsum = 0.f;
#pragma unroll
    for (int i = 0; i < 8; i++) {
        int c = cbase + i;
        float x0 = __half2float(a0p[i]) + b1[c];
        x0 = (x0 > 0.f) ? x0 : (__expf(x0) - 1.f);
        float x1 = __half2float(a1p[i]) + b1[256 + c];
        x1 = (x1 > 0.f) ? x1 : (__expf(x1) - 1.f);
        float val = w0 * x0 + w1 * x1 + skv[i] + skip_b[c];
        vals[i] = val;
        lsum += val;
    }
    float sum = wredsum(lsum);
    float mu = sum * (1.f / 256.f);
    float lvs = 0.f;
#pragma unroll
    for (int i = 0; i < 8; i++) {
        float dd = vals[i] - mu;
        lvs += dd * dd;
    }
    float vs = wredsum(lvs);
    float istd = rsqrtf(vs * (1.f / 256.f) + 1e-5f);

    __nv_bfloat16 oh[8], ol[8];
#pragma unroll
    for (int i = 0; i < 8; i++) {
        int c = cbase + i;
        float y = (vals[i] - mu) * istd * g[c] + bt[c];
        __nv_bfloat16 hi = __float2bfloat16(y);
        oh[i] = hi;
        ol[i] = __float2bfloat16(y - __bfloat162float(hi));
    }
    *(uint4*)(fxh + (long)v * 256 + cbase) = *(uint4*)oh;
    *(uint4*)(fxl + (long)v * 256 + cbase) = *(uint4*)ol;
}

// ========== conv2 aggregate + residual + LN2 (4-edge groups, unroll 2) ======
__global__ __launch_bounds__(256) void conv2_ln(const __half* __restrict__ h2,
                                                const float* __restrict__ h2fw,
                                                const float* __restrict__ as2,
                                                const float* __restrict__ ad2,
                                                const int* __restrict__ off,
                                                const int* __restrict__ csr,
                                                const float* __restrict__ b2,
                                                const float* __restrict__ finalb,
                                                const float* __restrict__ g2,
                                                const float* __restrict__ bt2,
                                                float* __restrict__ out) {
    __shared__ float sal[8][CAP];
    int gwarp = (blockIdx.x * blockDim.x + threadIdx.x) >> 5;
    int lane = threadIdx.x & 31;
    if (gwarp >= NN) return;
    int v = gwarp;
    float* sm = sal[threadIdx.x >> 5];
    int s0 = off[v], d = off[v + 1] - s0;
    int grp = lane >> 3, ch8 = lane & 7;
    float adv = ad2[v], asv = as2[v];
    float eself = lrelu(asv + adv);
    float m = eself;
    float inv;
    bool fits = (d <= CAP);

    if (fits) {
        for (int j = lane; j < d; j += 32) {
            int s = csr[s0 + j];
            float e = lrelu(as2[s] + adv);
            sm[j] = e;
            m = fmaxf(m, e);
        }
        m = wredmax(m);
        float den = (lane == 0) ? __expf(eself - m) : 0.f;
        for (int j = lane; j < d; j += 32) {
            float e = __expf(sm[j] - m);
            sm[j] = e;
            den += e;
        }
        den = wredsum(den);
        inv = 1.f / (den + 1e-16f);
        __syncwarp();
    } else {
        for (int j = lane; j < d; j += 32) {
            int s = csr[s0 + j];
            m = fmaxf(m, lrelu(as2[s] + adv));
        }
        m = wredmax(m);
        float den = (lane == 0) ? __expf(eself - m) : 0.f;
        for (int j = lane; j < d; j += 32) {
            int s = csr[s0 + j];
            den += __expf(lrelu(as2[s] + adv) - m);
        }
        den = wredsum(den);
        inv = 1.f / (den + 1e-16f);
    }

    float2 acc[4];
    acc[0] = acc[1] = acc[2] = acc[3] = make_float2(0.f, 0.f);
    if (grp == 0) {
        uint4 r = ((const uint4*)(h2 + (long)v * 64))[ch8];
        fma8(acc, r, __expf(eself - m) * inv);
    }
    if (fits) {
        int j = grp;
        for (; j + 4 < d; j += 8) {
            int sA = csr[s0 + j], sB = csr[s0 + j + 4];
            uint4 rA = ((const uint4*)(h2 + (long)sA * 64))[ch8];
            uint4 rB = ((const uint4*)(h2 + (long)sB * 64))[ch8];
            fma8(acc, rA, sm[j] * inv);
            fma8(acc, rB, sm[j + 4] * inv);
        }
        for (; j < d; j += 4) {
            int s = csr[s0 + j];
            uint4 r = ((const uint4*)(h2 + (long)s * 64))[ch8];
            fma8(acc, r, sm[j] * inv);
        }
    } else {
        for (int j = grp; j < d; j += 4) {
            int s = csr[s0 + j];
            uint4 r = ((const uint4*)(h2 + (long)s * 64))[ch8];
            float a = __expf(lrelu(as2[s] + adv) - m) * inv;
            fma8(acc, r, a);
        }
    }
#pragma unroll
    for (int i = 0; i < 4; i++) {
        acc[i].x += __shfl_xor_sync(0xffffffffu, acc[i].x, 8);
        acc[i].x += __shfl_xor_sync(0xffffffffu, acc[i].x, 16);
        acc[i].y += __shfl_xor_sync(0xffffffffu, acc[i].y, 8);
        acc[i].y += __shfl_xor_sync(0xffffffffu, acc[i].y, 16);
    }
    float vals[8];
    float lsum = 0.f;
#pragma unroll
    for (int i = 0; i < 4; i++) {
        int c = ch8 * 8 + 2 * i;
        float r0 = acc[i].x + b2[c] + h2fw[(long)v * 128 + 64 + c] + finalb[c];
        float r1 = acc[i].y + b2[c + 1] + h2fw[(long)v * 128 + 64 + c + 1] + finalb[c + 1];
        vals[2 * i] = r0;
        vals[2 * i + 1] = r1;
        lsum += r0 + r1;
    }
    float sum = wredsum(lsum) * 0.25f;
    float mu = sum * (1.f / 64.f);
    float lvs = 0.f;
#pragma unroll
    for (int i = 0; i < 8; i++) {
        float dd = vals[i] - mu;
        lvs += dd * dd;
    }
    float vs = wredsum(lvs) * 0.25f;
    float istd = rsqrtf(vs * (1.f / 64.f) + 1e-5f);
    if (grp == 0) {
        float o[8];
#pragma unroll
        for (int i = 0; i < 8; i++) {
            int c = ch8 * 8 + i;
            o[i] = (vals[i] - mu) * istd * g2[c] + bt2[c];
        }
        float4* op = (float4*)(out + (long)v * 64 + ch8 * 8);
        op[0] = make_float4(o[0], o[1], o[2], o[3]);
        op[1] = make_float4(o[4], o[5], o[6], o[7]);
    }
}

__global__ void write_w(const float* __restrict__ ha, float* __restrict__ out) {
    if (threadIdx.x == 0) {
        float a0 = ha[0], a1 = ha[1];
        float mx = fmaxf(a0, a1);
        float e0 = __expf(a0 - mx), e1 = __expf(a1 - mx);
        float inv = 1.f / (e0 + e1);
        out[NN * 64 + 0] = e0 * inv;
        out[NN * 64 + 1] = e1 * inv;
    }
}

// ================= launch ===================================================
extern "C" void kernel_launch(void* const* d_in, const int* in_sizes, int n_in,
                              void* d_out, int out_size) {
    const float* x = (const float*)d_in[0];
    const int* ei = (const int*)d_in[1];
    const int* ei2 = (const int*)d_in[2];
    const float* W1 = (const float*)d_in[3];
    const float* att_src1 = (const float*)d_in[4];
    const float* att_dst1 = (const float*)d_in[5];
    const float* b1 = (const float*)d_in[6];
    const float* W2 = (const float*)d_in[7];
    const float* att_src2 = (const float*)d_in[8];
    const float* att_dst2 = (const float*)d_in[9];
    const float* b2 = (const float*)d_in[10];
    const float* ha = (const float*)d_in[11];
    const float* skipW = (const float*)d_in[12];
    const float* skipb = (const float*)d_in[13];
    const float* finalW = (const float*)d_in[14];
    const float* finalb = (const float*)d_in[15];
    const float* ln1g = (const float*)d_in[16];
    const float* ln1b = (const float*)d_in[17];
    const float* ln2g = (const float*)d_in[18];
    const float* ln2b = (const float*)d_in[19];
    float* out = (float*)d_out;

    GS* g = nullptr;
    cudaGetSymbolAddress((void**)&g, gs);

    static cudaStream_t sB = nullptr;
    static cudaEvent_t evFork = nullptr, evJoin = nullptr;
    if (!sB) {
        cudaStreamCreateWithFlags(&sB, cudaStreamNonBlocking);
        cudaEventCreateWithFlags(&evFork, cudaEventDisableTiming);
        cudaEventCreateWithFlags(&evJoin, cudaEventDisableTiming);
    }

    const int GSMEM = 2 * 40960;
    const int GSMEMF = 3 * 20480;
    cudaFuncSetAttribute(hmma_gemm, cudaFuncAttributeMaxDynamicSharedMemorySize, GSMEM);
    cudaFuncSetAttribute(hmma_gemm_f16, cudaFuncAttributeMaxDynamicSharedMemorySize, GSMEMF);

    const int TB = 256;
    int nb = (NN + TB - 1) / TB;
    int wb = (NN + 7) / 8;
    int eb2 = (2 * EE + TB - 1) / TB;

    // ---- fork: CSR build + pack_B2 on stream B ----
    cudaEventRecord(evFork, 0);
    cudaStreamWaitEvent(sB, evFork, 0);
    pack_B2<<<(128 * 256 + TB - 1) / TB, TB, 0, sB>>>(W2, finalW, g->B2h, g->B2l);
    zero_int<<<(2 * NN + TB - 1) / TB, TB, 0, sB>>>(g->deg0, 2 * NN);
    hist2<<<eb2, TB, 0, sB>>>(ei + EE, ei2 + EE, g->deg0, g->deg1);
    {
        dim3 gp(SBLK, 2);
        scan_part<<<gp, 256, 0, sB>>>(g->deg0, g->deg1, g->bsum);
        scan_mid<<<2, 256, 0, sB>>>(g->bsum, g->off0, g->off1);
        scan_emit<<<gp, 256, 0, sB>>>(g->deg0, g->deg1, g->bsum,
                                      g->off0, g->cur0, g->off1, g->cur1);
    }
    scatter2<<<eb2, TB, 0, sB>>>(ei, ei2, g->cur0, g->cur1, g->csr0, g->csr1);
    cudaEventRecord(evJoin, sB);

    // ---- main stream: operand prep + GEMM1 + logits ----
    split_x<<<(NN * 256 + TB - 1) / TB, TB>>>(x, g->xf, NN * 256);
    pack_B1f<<<(768 * 256 + TB - 1) / TB, TB>>>(W1, skipW, g->B1f);
    {
        dim3 grid(6, (NN + 127) / 128);
        hmma_gemm_f16<<<grid, 256, GSMEMF>>>(g->xf, g->B1f, g->h0f, g->h1f, g->skb, NN);
    }
    {
        dim3 grid((NN * 8 + TB - 1) / TB, 2);
        logits8_2<<<grid, TB>>>((const __half2*)g->h0f, (const __half2*)g->h1f,
                                att_src1, att_dst1, g->as0, g->ad0, g->as1, g->ad1);
    }

    // ---- join: aggregation needs CSR ----
    cudaStreamWaitEvent(0, evJoin, 0);
    {
        dim3 grid(wb, 2);
        gat_agg8_2<<<grid, TB>>>(g->h0f, g->h1f, g->as0, g->ad0, g->as1, g->ad1,
                                 g->off0, g->csr0, g->off1, g->csr1, g->agg0f, g->agg1f);
    }

    combine_ln<<<wb, TB>>>(g->agg0f, g->agg1f, g->skb, b1, skipb, ha, ln1g, ln1b,
                           g->fxh, g->fxl);

    // GEMM2 (bf16 split): first @ [W2 | final_W] -> h2fw (fp32) + h2f (fp16 mirror)
    {
        dim3 grid(1, (NN + 127) / 128);
        hmma_gemm<<<grid, 256, GSMEM>>>(g->fxh, g->fxl, g->B2h, g->B2l, g->h2fw, g->h2f,
                                        NN, 128);
    }

    logits1<<<nb, TB>>>((const __half2*)g->h2f, att_src2, att_dst2, g->as2, g->ad2);
    conv2_ln<<<wb, TB>>>(g->h2f, g->h2fw, g->as2, g->ad2, g->off0, g->csr0,
                         b2, finalb, ln2g, ln2b, out);
    write_w<<<1, 32>>>(ha, out);
}

// round 17
// speedup vs baseline: 1.0542x; 1.0542x over previous
#include <cuda_runtime.h>
#include <cuda_bf16.h>
#include <cuda_fp16.h>
#include <math.h>
#include <stdint.h>

#define NN 50000
#define EE 800000
#define CAP 64
#define SBLK 196  // ceil(50000/256)

// ================= scratch ==================================================
struct GS {
    float skb[(size_t)NN * 256];
    float agg0[(size_t)NN * 256];
    float agg1[(size_t)NN * 256];
    float h2fw[(size_t)NN * 128];
    __half h0f[(size_t)NN * 256];
    __half h1f[(size_t)NN * 256];
    __half h2f[(size_t)NN * 64];
    float as0[NN * 8], ad0[NN * 8], as1[NN * 8], ad1[NN * 8];
    float as2[NN], ad2[NN];
    __half xf[(size_t)NN * 256];
    __nv_bfloat16 fxh[(size_t)NN * 256], fxl[(size_t)NN * 256];
    __half B1f[768 * 256];
    __nv_bfloat16 B2h[128 * 256], B2l[128 * 256];
    int deg0[NN], deg1[NN];
    int off0[NN + 1], off1[NN + 1];
    int cur0[NN], cur1[NN];
    int bsum[2 * SBLK];
    int csr0[EE], csr1[EE];
};
__device__ GS gs;

// ================= helpers ==================================================
__device__ __forceinline__ float wredsum(float v) {
#pragma unroll
    for (int o = 16; o; o >>= 1) v += __shfl_xor_sync(0xffffffffu, v, o);
    return v;
}
__device__ __forceinline__ float wredmax(float v) {
#pragma unroll
    for (int o = 16; o; o >>= 1) v = fmaxf(v, __shfl_xor_sync(0xffffffffu, v, o));
    return v;
}
__device__ __forceinline__ int wscan_incl(int v, int lane) {
#pragma unroll
    for (int o = 1; o < 32; o <<= 1) {
        int t = __shfl_up_sync(0xffffffffu, v, o);
        if (lane >= o) v += t;
    }
    return v;
}
__device__ __forceinline__ float lrelu(float x) { return fmaxf(x, 0.2f * x); }
__device__ __forceinline__ uint32_t smem_u32(const void* p) {
    uint32_t a;
    asm("{ .reg .u64 t; cvta.to.shared.u64 t, %1; cvt.u32.u64 %0, t; }" : "=r"(a) : "l"(p));
    return a;
}
__device__ __forceinline__ void cp16(uint32_t dst, const void* src, bool v) {
    int bytes = v ? 16 : 0;
    asm volatile("cp.async.cg.shared.global [%0], [%1], 16, %2;\n"
                 :: "r"(dst), "l"(src), "r"(bytes));
}
__device__ __forceinline__ void ldsm4(uint32_t* r, uint32_t addr) {
    asm volatile("ldmatrix.sync.aligned.m8n8.x4.shared.b16 {%0,%1,%2,%3}, [%4];\n"
                 : "=r"(r[0]), "=r"(r[1]), "=r"(r[2]), "=r"(r[3]) : "r"(addr));
}
__device__ __forceinline__ void mma_bf16(float* d, const uint32_t* a, uint32_t b0, uint32_t b1) {
    asm volatile(
        "mma.sync.aligned.m16n8k16.row.col.f32.bf16.bf16.f32 "
        "{%0,%1,%2,%3}, {%4,%5,%6,%7}, {%8,%9}, {%0,%1,%2,%3};\n"
        : "+f"(d[0]), "+f"(d[1]), "+f"(d[2]), "+f"(d[3])
        : "r"(a[0]), "r"(a[1]), "r"(a[2]), "r"(a[3]), "r"(b0), "r"(b1));
}
__device__ __forceinline__ void mma_f16(float* d, const uint32_t* a, uint32_t b0, uint32_t b1) {
    asm volatile(
        "mma.sync.aligned.m16n8k16.row.col.f32.f16.f16.f32 "
        "{%0,%1,%2,%3}, {%4,%5,%6,%7}, {%8,%9}, {%0,%1,%2,%3};\n"
        : "+f"(d[0]), "+f"(d[1]), "+f"(d[2]), "+f"(d[3])
        : "r"(a[0]), "r"(a[1]), "r"(a[2]), "r"(a[3]), "r"(b0), "r"(b1));
}
__device__ __forceinline__ void fma8(float2* acc, uint4 r, float a) {
    float2 x0 = __half22float2(*(__half2*)&r.x);
    float2 x1 = __half22float2(*(__half2*)&r.y);
    float2 x2 = __half22float2(*(__half2*)&r.z);
    float2 x3 = __half22float2(*(__half2*)&r.w);
    acc[0].x += a * x0.x; acc[0].y += a * x0.y;
    acc[1].x += a * x1.x; acc[1].y += a * x1.y;
    acc[2].x += a * x2.x; acc[2].y += a * x2.y;
    acc[3].x += a * x3.x; acc[3].y += a * x3.y;
}

// ================= CSR build ================================================
__global__ void zero_int(int* p, int n) {
    int i = blockIdx.x * blockDim.x + threadIdx.x;
    if (i < n) p[i] = 0;
}
__global__ void hist2(const int* __restrict__ d0, const int* __restrict__ d1,
                      int* __restrict__ deg0, int* __restrict__ deg1) {
    int i = blockIdx.x * blockDim.x + threadIdx.x;
    if (i < EE) atomicAdd(&deg0[d0[i]], 1);
    else if (i < 2 * EE) atomicAdd(&deg1[d1[i - EE]], 1);
}
__global__ void scan_part(const int* __restrict__ deg0, const int* __restrict__ deg1,
                          int* __restrict__ bsum) {
    __shared__ int wsum[8];
    const int* deg = blockIdx.y ? deg1 : deg0;
    int tid = threadIdx.x, lane = tid & 31, warp = tid >> 5;
    int i = blockIdx.x * 256 + tid;
    int v = (i < NN) ? deg[i] : 0;
#pragma unroll
    for (int o = 16; o; o >>= 1) v += __shfl_xor_sync(0xffffffffu, v, o);
    if (lane == 0) wsum[warp] = v;
    __syncthreads();
    if (tid == 0) {
        int t = 0;
#pragma unroll
        for (int w = 0; w < 8; w++) t += wsum[w];
        bsum[blockIdx.y * SBLK + blockIdx.x] = t;
    }
}
__global__ void scan_mid(int* __restrict__ bsum, int* __restrict__ off0, int* __restrict__ off1) {
    __shared__ int wpre[8];
    int g = blockIdx.x;
    int tid = threadIdx.x, lane = tid & 31, warp = tid >> 5;
    int v = (tid < SBLK) ? bsum[g * SBLK + tid] : 0;
    int incl = wscan_incl(v, lane);
    if (lane == 31) wpre[warp] = incl;
    __syncthreads();
    if (warp == 0) {
        int w = (lane < 8) ? wpre[lane] : 0;
        int wi = wscan_incl(w, lane);
        if (lane < 8) wpre[lane] = wi - w;
    }
    __syncthreads();
    int excl = wpre[warp] + incl - v;
    if (tid < SBLK) bsum[g * SBLK + tid] = excl;
    if (tid == SBLK - 1) {
        int total = excl + v;
        if (g == 0) off0[NN] = total; else off1[NN] = total;
    }
}
__global__ void scan_emit(const int* __restrict__ deg0, const int* __restrict__ deg1,
                          const int* __restrict__ bsum,
                          int* __restrict__ off0, int* __restrict__ cur0,
                          int* __restrict__ off1, int* __restrict__ cur1) {
    __shared__ int wpre[8];
    int g = blockIdx.y;
    const int* deg = g ? deg1 : deg0;
    int* off = g ? off1 : off0;
    int* cur = g ? cur1 : cur0;
    int tid = threadIdx.x, lane = tid & 31, warp = tid >> 5;
    int i = blockIdx.x * 256 + tid;
    int v = (i < NN) ? deg[i] : 0;
    int incl = wscan_incl(v, lane);
    if (lane == 31) wpre[warp] = incl;
    __syncthreads();
    if (warp == 0) {
        int w = (lane < 8) ? wpre[lane] : 0;
        int wi = wscan_incl(w, lane);
        if (lane < 8) wpre[lane] = wi - w;
    }
    __syncthreads();
    int excl = bsum[g * SBLK + blockIdx.x] + wpre[warp] + incl - v;
    if (i < NN) {
        off[i] = excl;
        cur[i] = excl;
    }
}
__global__ void scatter2(const int* __restrict__ e0, const int* __restrict__ e1,
                         int* __restrict__ cur0, int* __restrict__ cur1,
                         int* __restrict__ csr0, int* __restrict__ csr1) {
    int i = blockIdx.x * blockDim.x + threadIdx.x;
    if (i < EE) {
        int d = e0[EE + i];
        int p = atomicAdd(&cur0[d], 1);
        csr0[p] = e0[i];
    } else if (i < 2 * EE) {
        int j = i - EE;
        int d = e1[EE + j];
        int p = atomicAdd(&cur1[d], 1);
        csr1[p] = e1[j];
    }
}

// ================= operand packing ==========================================
__global__ void split_x(const float* __restrict__ x, __half* __restrict__ xf, int n) {
    int i = blockIdx.x * blockDim.x + threadIdx.x;
    if (i < n) xf[i] = __float2half_rn(x[i]);
}
__global__ void pack_B1f(const float* __restrict__ W1, const float* __restrict__ skipW,
                         __half* __restrict__ Bf) {
    int i = blockIdx.x * blockDim.x + threadIdx.x;
    if (i >= 768 * 256) return;
    int n = i / 256, k = i % 256;
    float v;
    if (n < 256) v = W1[k * 256 + n];
    else if (n < 512) v = W1[65536 + k * 256 + (n - 256)];
    else v = skipW[k * 256 + (n - 512)];
    Bf[i] = __float2half_rn(v);
}
__global__ void pack_B2(const float* __restrict__ W2, const float* __restrict__ finalW,
                        __nv_bfloat16* __restrict__ Bh, __nv_bfloat16* __restrict__ Bl) {
    int i = blockIdx.x * blockDim.x + threadIdx.x;
    if (i >= 128 * 256) return;
    int n = i / 256, k = i % 256;
    float v = (n < 64) ? W2[k * 64 + n] : finalW[k * 64 + (n - 64)];
    __nv_bfloat16 h = __float2bfloat16(v);
    Bh[i] = h;
    Bl[i] = __float2bfloat16(v - __bfloat162float(h));
}

// ====== fp16 single-pass HMMA GEMM: A[M,256] @ B[768,256]^T =================
__global__ __launch_bounds__(256, 2) void hmma_gemm_f16(
    const __half* __restrict__ A, const __half* __restrict__ B,
    __half* __restrict__ H0, __half* __restrict__ H1, float* __restrict__ C2, int M) {
    extern __shared__ char sm[];
    const int tid = threadIdx.x, lane = tid & 31, warp = tid >> 5;
    const int wm = warp & 1, wn = warp >> 1;
    const int m0 = blockIdx.y * 128, n0 = blockIdx.x * 128;
    uint32_t sbase = smem_u32(sm);

    float acc[4][4][4];
#pragma unroll
    for (int a = 0; a < 4; a++)
#pragma unroll
        for (int b = 0; b < 4; b++)
#pragma unroll
            for (int q = 0; q < 4; q++) acc[a][b][q] = 0.f;

#define LOADF(c, s)                                                               \
    do {                                                                          \
        uint32_t sb_ = sbase + (s) * 20480;                                       \
        _Pragma("unroll") for (int it = 0; it < 2; it++) {                        \
            int idx = tid + it * 256;                                             \
            int row = idx >> 2, kc = idx & 3;                                     \
            uint32_t so = row * 80 + kc * 16;                                     \
            bool va = (m0 + row) < M;                                             \
            long ga = (long)(m0 + row) * 256 + (c) * 32 + kc * 8;                 \
            if (!va) ga = 0;                                                      \
            cp16(sb_ + so, A + ga, va);                                           \
            long gb = (long)(n0 + row) * 256 + (c) * 32 + kc * 8;                 \
            cp16(sb_ + 10240 + so, B + gb, true);                                 \
        }                                                                         \
        asm volatile("cp.async.commit_group;\n" ::: "memory");                    \
    } while (0)

    LOADF(0, 0);
    LOADF(1, 1);
    for (int c = 0; c < 8; c++) {
        if (c + 2 < 8) LOADF(c + 2, (c + 2) % 3);
        if (c < 6) asm volatile("cp.async.wait_group 2;\n" ::: "memory");
        else if (c == 6) asm volatile("cp.async.wait_group 1;\n" ::: "memory");
        else asm volatile("cp.async.wait_group 0;\n" ::: "memory");
        __syncthreads();
        uint32_t sb = sbase + (c % 3) * 20480;
#pragma unroll
        for (int ks = 0; ks < 2; ks++) {
            uint32_t ah[4][4], bh[2][4];
            int acol = ks * 16 + 8 * (lane >> 4);
            int arowl = (lane & 15);
#pragma unroll
            for (int mf = 0; mf < 4; mf++) {
                int arow = wm * 64 + mf * 16 + arowl;
                ldsm4(ah[mf], sb + arow * 80 + acol * 2);
            }
            int bcol = ks * 16 + 8 * ((lane >> 3) & 1);
            int browl = (lane & 7) + 8 * (lane >> 4);
#pragma unroll
            for (int p = 0; p < 2; p++) {
                int brow = wn * 32 + p * 16 + browl;
                ldsm4(bh[p], sb + 10240 + brow * 80 + bcol * 2);
            }
#pragma unroll
            for (int mf = 0; mf < 4; mf++)
#pragma unroll
                for (int p = 0; p < 2; p++)
#pragma unroll
                    for (int sub = 0; sub < 2; sub++) {
                        int nf = p * 2 + sub;
                        mma_f16(acc[mf][nf], ah[mf], bh[p][sub * 2], bh[p][sub * 2 + 1]);
                    }
        }
        __syncthreads();
    }
#undef LOADF

    int bucket = n0 >> 8;
    int cb = n0 & 255;
    int group = lane >> 2, q = lane & 3;
    if (bucket < 2) {
        __half2* H = (__half2*)((bucket == 0) ? H0 : H1);
#pragma unroll
        for (int mf = 0; mf < 4; mf++) {
            int r0 = m0 + wm * 64 + mf * 16 + group;
#pragma unroll
            for (int nf = 0; nf < 4; nf++) {
                int col = cb + wn * 32 + nf * 8 + q * 2;
                if (r0 < M)
                    H[(long)r0 * 128 + col / 2] =
                        __floats2half2_rn(acc[mf][nf][0], acc[mf][nf][1]);
                if (r0 + 8 < M)
                    H[(long)(r0 + 8) * 128 + col / 2] =
                        __floats2half2_rn(acc[mf][nf][2], acc[mf][nf][3]);
            }
        }
    } else {
#pragma unroll
        for (int mf = 0; mf < 4; mf++) {
            int r0 = m0 + wm * 64 + mf * 16 + group;
#pragma unroll
            for (int nf = 0; nf < 4; nf++) {
                int col = cb + wn * 32 + nf * 8 + q * 2;
                if (r0 < M)
                    *(float2*)(C2 + (long)r0 * 256 + col) =
                        make_float2(acc[mf][nf][0], acc[mf][nf][1]);
                if (r0 + 8 < M)
                    *(float2*)(C2 + (long)(r0 + 8) * 256 + col) =
                        make_float2(acc[mf][nf][2], acc[mf][nf][3]);
            }
        }
    }
}

// ====== bf16-split HMMA GEMM (3 MMA): fp32 out + fp16 mirror cols<64 ========
__global__ __launch_bounds__(256, 2) void hmma_gemm(
    const __nv_bfloat16* __restrict__ Ah, const __nv_bfloat16* __restrict__ Al,
    const __nv_bfloat16* __restrict__ Bh, const __nv_bfloat16* __restrict__ Bl,
    float* __restrict__ C, __half* __restrict__ Hf, int M, int split) {
    extern __shared__ char sm[];
    const int tid = threadIdx.x, lane = tid & 31, warp = tid >> 5;
    const int wm = warp & 1, wn = warp >> 1;
    const int m0 = blockIdx.y * 128, n0 = blockIdx.x * 128;
    uint32_t sbase = smem_u32(sm);

    float acc[4][4][4];
#pragma unroll
    for (int a = 0; a < 4; a++)
#pragma unroll
        for (int b = 0; b < 4; b++)
#pragma unroll
            for (int q = 0; q < 4; q++) acc[a][b][q] = 0.f;

#define LOAD_STAGE(c, s)                                                          \
    do {                                                                          \
        uint32_t sb_ = sbase + (s) * 40960;                                       \
        _Pragma("unroll") for (int it = 0; it < 2; it++) {                        \
            int idx = tid + it * 256;                                             \
            int row = idx >> 2, kc = idx & 3;                                     \
            uint32_t so = row * 80 + kc * 16;                                     \
            bool va = (m0 + row) < M;                                             \
            long ga = (long)(m0 + row) * 256 + (c) * 32 + kc * 8;                 \
            if (!va) ga = 0;                                                      \
            cp16(sb_ + so, Ah + ga, va);                                          \
            cp16(sb_ + 10240 + so, Al + ga, va);                                  \
            long gb = (long)(n0 + row) * 256 + (c) * 32 + kc * 8;                 \
            cp16(sb_ + 20480 + so, Bh + gb, true);                                \
            cp16(sb_ + 30720 + so, Bl + gb, true);                                \
        }                                                                         \
        asm volatile("cp.async.commit_group;\n" ::: "memory");                    \
    } while (0)

    LOAD_STAGE(0, 0);
    for (int c = 0; c < 8; c++) {
        if (c < 7) {
            LOAD_STAGE(c + 1, (c + 1) & 1);
            asm volatile("cp.async.wait_group 1;\n" ::: "memory");
        } else {
            asm volatile("cp.async.wait_group 0;\n" ::: "memory");
        }
        __syncthreads();
        uint32_t sb = sbase + (c & 1) * 40960;
#pragma unroll
        for (int ks = 0; ks < 2; ks++) {
            uint32_t ah[4][4], al[4][4], bhf[2][4], blf[2][4];
            int acol = ks * 16 + 8 * (lane >> 4);
            int arowl = (lane & 15);
#pragma unroll
            for (int mf = 0; mf < 4; mf++) {
                int arow = wm * 64 + mf * 16 + arowl;
                uint32_t ad = sb + arow * 80 + acol * 2;
                ldsm4(ah[mf], ad);
                ldsm4(al[mf], ad + 10240);
            }
            int bcol = ks * 16 + 8 * ((lane >> 3) & 1);
            int browl = (lane & 7) + 8 * (lane >> 4);
#pragma unroll
            for (int p = 0; p < 2; p++) {
                int brow = wn * 32 + p * 16 + browl;
                uint32_t bd = sb + 20480 + brow * 80 + bcol * 2;
                ldsm4(bhf[p], bd);
                ldsm4(blf[p], bd + 10240);
            }
#pragma unroll
            for (int mf = 0; mf < 4; mf++)
#pragma unroll
                for (int p = 0; p < 2; p++)
#pragma unroll
                    for (int sub = 0; sub < 2; sub++) {
                        int nf = p * 2 + sub;
                        uint32_t h0 = bhf[p][sub * 2], h1 = bhf[p][sub * 2 + 1];
                        uint32_t l0 = blf[p][sub * 2], l1 = blf[p][sub * 2 + 1];
                        mma_bf16(acc[mf][nf], ah[mf], h0, h1);
                        mma_bf16(acc[mf][nf], ah[mf], l0, l1);
                        mma_bf16(acc[mf][nf], al[mf], h0, h1);
                    }
        }
        __syncthreads();
    }
#undef LOAD_STAGE

    int cb = n0 % split;
    int group = lane >> 2, q = lane & 3;
#pragma unroll
    for (int mf = 0; mf < 4; mf++) {
        int r0 = m0 + wm * 64 + mf * 16 + group;
#pragma unroll
        for (int nf = 0; nf < 4; nf++) {
            int col = cb + wn * 32 + nf * 8 + q * 2;
            bool lo = (col < 64) && Hf;
            if (r0 < M) {
                if (lo)
                    ((__half2*)Hf)[(long)r0 * 32 + col / 2] =
                        __floats2half2_rn(acc[mf][nf][0], acc[mf][nf][1]);
                *(float2*)(C + (long)r0 * split + col) =
                    make_float2(acc[mf][nf][0], acc[mf][nf][1]);
            }
            if (r0 + 8 < M) {
                if (lo)
                    ((__half2*)Hf)[(long)(r0 + 8) * 32 + col / 2] =
                        __floats2half2_rn(acc[mf][nf][2], acc[mf][nf][3]);
                *(float2*)(C + (long)(r0 + 8) * split + col) =
                    make_float2(acc[mf][nf][2], acc[mf][nf][3]);
            }
        }
    }
}

// ================= attention logits (both hops in one launch) ===============
__global__ void logits8_2(const __half2* __restrict__ h0, const __half2* __restrict__ h1,
                          const float* __restrict__ a_src, const float* __restrict__ a_dst,
                          float* __restrict__ as0, float* __restrict__ ad0,
                          float* __restrict__ as1, float* __restrict__ ad1) {
    int t = blockIdx.x * blockDim.x + threadIdx.x;
    if (t >= NN * 8) return;
    int hop = blockIdx.y;
    const __half2* h = hop ? h1 : h0;
    float* as = hop ? as1 : as0;
    float* ad = hop ? ad1 : ad0;
    int v = t >> 3, k = t & 7;
    const __half2* hr = h + (long)v * 128 + k * 16;
    const float* sv = a_src + hop * 256 + k * 32;
    const float* dv = a_dst + hop * 256 + k * 32;
    float s = 0.f, d = 0.f;
#pragma unroll
    for (int c = 0; c < 16; c++) {
        float2 hv = __half22float2(hr[c]);
        s += hv.x * sv[2 * c] + hv.y * sv[2 * c + 1];
        d += hv.x * dv[2 * c] + hv.y * dv[2 * c + 1];
    }
    as[t] = s;
    ad[t] = d;
}
__global__ void logits1(const __half2* __restrict__ h2, const float* __restrict__ a_src,
                        const float* __restrict__ a_dst, float* __restrict__ as,
                        float* __restrict__ ad) {
    int v = blockIdx.x * blockDim.x + threadIdx.x;
    if (v >= NN) return;
    const __half2* hr = h2 + (long)v * 32;
    float s = 0.f, d = 0.f;
#pragma unroll
    for (int c = 0; c < 32; c++) {
        float2 hv = __half22float2(hr[c]);
        s += hv.x * a_src[2 * c] + hv.y * a_src[2 * c + 1];
        d += hv.x * a_dst[2 * c] + hv.y * a_dst[2 * c + 1];
    }
    as[v] = s;
    ad[v] = d;
}

// ====== GAT aggregation: both hops, warp/dst, lane = 8 contiguous channels ==
__global__ __launch_bounds__(256) void gat_agg8_2(
    const __half* __restrict__ h0p, const __half* __restrict__ h1p,
    const float* __restrict__ as0, const float* __restrict__ ad0,
    const float* __restrict__ as1, const float* __restrict__ ad1,
    const int* __restrict__ off0, const int* __restrict__ csr0,
    const int* __restrict__ off1, const int* __restrict__ csr1,
    float* __restrict__ agg0, float* __restrict__ agg1) {
    __shared__ float sal[8][CAP * 9];
    int gwarp = (blockIdx.x * blockDim.x + threadIdx.x) >> 5;
    int lane = threadIdx.x & 31;
    if (gwarp >= NN) return;
    int hop = blockIdx.y;
    const __half* h = hop ? h1p : h0p;
    const float* as = hop ? as1 : as0;
    const float* ad = hop ? ad1 : ad0;
    const int* off = hop ? off1 : off0;
    const int* csr = hop ? csr1 : csr0;
    float* out = hop ? agg1 : agg0;

    int v = gwarp;
    float* sm = sal[threadIdx.x >> 5];
    int s0 = off[v], d = off[v + 1] - s0;
    int head = lane >> 2;

    float adv[8], asv[8];
    {
        float4 a0 = *(const float4*)(ad + v * 8);
        float4 a1 = *(const float4*)(ad + v * 8 + 4);
        adv[0] = a0.x; adv[1] = a0.y; adv[2] = a0.z; adv[3] = a0.w;
        adv[4] = a1.x; adv[5] = a1.y; adv[6] = a1.z; adv[7] = a1.w;
        float4 b0 = *(const float4*)(as + v * 8);
        float4 b1 = *(const float4*)(as + v * 8 + 4);
        asv[0] = b0.x; asv[1] = b0.y; asv[2] = b0.z; asv[3] = b0.w;
        asv[4] = b1.x; asv[5] = b1.y; asv[6] = b1.z; asv[7] = b1.w;
    }
    float m[8], den[8];
#pragma unroll
    for (int k = 0; k < 8; k++) m[k] = lrelu(asv[k] + adv[k]);

    bool fits = (d <= CAP);
    if (fits) {
        for (int j = lane; j < d; j += 32) {
            int s = csr[s0 + j];
            float4 a0 = *(const float4*)(as + s * 8);
            float4 a1 = *(const float4*)(as + s * 8 + 4);
            float ev[8] = {a0.x, a0.y, a0.z, a0.w, a1.x, a1.y, a1.z, a1.w};
#pragma unroll
            for (int k = 0; k < 8; k++) {
                float e = lrelu(ev[k] + adv[k]);
                sm[j * 9 + k] = e;
                m[k] = fmaxf(m[k], e);
            }
        }
#pragma unroll
        for (int k = 0; k < 8; k++) m[k] = wredmax(m[k]);
#pragma unroll
        for (int k = 0; k < 8; k++)
            den[k] = (lane == 0) ? __expf(lrelu(asv[k] + adv[k]) - m[k]) : 0.f;
        for (int j = lane; j < d; j += 32) {
#pragma unroll
            for (int k = 0; k < 8; k++) {
                float e = __expf(sm[j * 9 + k] - m[k]);
                sm[j * 9 + k] = e;
                den[k] += e;
            }
        }
#pragma unroll
        for (int k = 0; k < 8; k++) {
            den[k] = wredsum(den[k]);
            den[k] = 1.f / (den[k] + 1e-16f);
        }
        __syncwarp();
    } else {
        for (int j = lane; j < d; j += 32) {
            int s = csr[s0 + j];
#pragma unroll
            for (int k = 0; k < 8; k++) m[k] = fmaxf(m[k], lrelu(as[s * 8 + k] + adv[k]));
        }
#pragma unroll
        for (int k = 0; k < 8; k++) m[k] = wredmax(m[k]);
#pragma unroll
        for (int k = 0; k < 8; k++)
            den[k] = (lane == 0) ? __expf(lrelu(asv[k] + adv[k]) - m[k]) : 0.f;
        for (int j = lane; j < d; j += 32) {
            int s = csr[s0 + j];
#pragma unroll
            for (int k = 0; k < 8; k++)
                den[k] += __expf(lrelu(as[s * 8 + k] + adv[k]) - m[k]);
        }
#pragma unroll
        for (int k = 0; k < 8; k++) {
            den[k] = wredsum(den[k]);
            den[k] = 1.f / (den[k] + 1e-16f);
        }
    }

    float msel = m[0], dsel = den[0], advsel = adv[0], slsel = asv[0] + adv[0];
#pragma unroll
    for (int k = 1; k < 8; k++)
        if (head == k) { msel = m[k]; dsel = den[k]; advsel = adv[k]; slsel = asv[k] + adv[k]; }
    float esel = __expf(lrelu(slsel) - msel) * dsel;

    float2 acc[4];
    {
        uint4 r = *((const uint4*)(h + (long)v * 256) + lane);
        acc[0] = acc[1] = acc[2] = acc[3] = make_float2(0.f, 0.f);
        fma8(acc, r, esel);
    }
    if (fits) {
        int j = 0;
        for (; j + 8 <= d; j += 8) {
            int sx[8];
#pragma unroll
            for (int u = 0; u < 8; u++) sx[u] = csr[s0 + j + u];
            uint4 r[8];
#pragma unroll
            for (int u = 0; u < 8; u++)
                r[u] = *((const uint4*)(h + (long)sx[u] * 256) + lane);
#pragma unroll
            for (int u = 0; u < 8; u++) fma8(acc, r[u], sm[(j + u) * 9 + head] * dsel);
        }
        for (; j + 4 <= d; j += 4) {
            int sx[4];
#pragma unroll
            for (int u = 0; u < 4; u++) sx[u] = csr[s0 + j + u];
            uint4 r[4];
#pragma unroll
            for (int u = 0; u < 4; u++)
                r[u] = *((const uint4*)(h + (long)sx[u] * 256) + lane);
#pragma unroll
            for (int u = 0; u < 4; u++) fma8(acc, r[u], sm[(j + u) * 9 + head] * dsel);
        }
        for (; j < d; j++) {
            int s = csr[s0 + j];
            uint4 r = *((const uint4*)(h + (long)s * 256) + lane);
            fma8(acc, r, sm[j * 9 + head] * dsel);
        }
    } else {
        for (int j = 0; j < d; j++) {
            int s = csr[s0 + j];
            uint4 r = *((const uint4*)(h + (long)s * 256) + lane);
            float a = __expf(lrelu(as[s * 8 + head] + advsel) - msel) * dsel;
            fma8(acc, r, a);
        }
    }
    float4* op = (float4*)(out + (long)v * 256 + lane * 8);
    op[0] = make_float4(acc[0].x, acc[0].y, acc[1].x, acc[1].y);
    op[1] = make_float4(acc[2].x, acc[2].y, acc[3].x, acc[3].y);
}

// ========== hop combine + skip + LN1 -> bf16 split for GEMM2 ================
__global__ __launch_bounds__(256) void combine_ln(const float* __restrict__ agg0,
                                                  const float* __restrict__ agg1,
                                                  const float* __restrict__ skb,
                                                  const float* __restrict__ b1,
                                                  const float* __restrict__ skip_b,
                                                  const float* __restrict__ ha,
                                                  const float* __restrict__ g,
                                                  const float* __restrict__ bt,
                                                  __nv_bfloat16* __restrict__ fxh,
                                                  __nv_bfloat16* __restrict__ fxl) {
    int warp = (blockIdx.x * blockDim.x + threadIdx.x) >> 5;
    int lane = threadIdx.x & 31;
    if (warp >= NN) return;
    int v = warp;
    float a0h = ha[0], a1h = ha[1];
    float mx = fmaxf(a0h, a1h);
    float e0 = __expf(a0h - mx), e1 = __expf(a1h - mx);
    float inv = 1.f / (e0 + e1);
    float w0 = e0 * inv, w1 = e1 * inv;

    float vals[8];
    float sum = 0.f;
#pragma unroll
    for (int k = 0; k < 8; k++) {
        int c = k * 32 + lane;
        float x0 = agg0[(long)v * 256 + c] + b1[c];
        x0 = (x0 > 0.f) ? x0 : (__expf(x0) - 1.f);
        float x1 = agg1[(long)v * 256 + c] + b1[256 + c];
        x1 = (x1 > 0.f) ? x1 : (__expf(x1) - 1.f);
        float val = w0 * x0 + w1 * x1 + skb[(long)v * 256 + c] + skip_b[c];
        vals[k] = val;
        sum += val;
    }
    sum = wredsum(sum);
    float mu = sum * (1.f / 256.f);
    float vs = 0.f;
#pragma unroll
    for (int k = 0; k < 8; k++) {
        float dd = vals[k] - mu;
        vs += dd * dd;
    }
    vs = wredsum(vs);
    float istd = rsqrtf(vs * (1.f / 256.f) + 1e-5f);
#pragma unroll
    for (int k = 0; k < 8; k++) {
        int c = k * 32 + lane;
        float y = (vals[k] - mu) * istd * g[c] + bt[c];
        __nv_bfloat16 hi = __float2bfloat16(y);
        fxh[(long)v * 256 + c] = hi;
        fxl[(long)v * 256 + c] = __float2bfloat16(y - __bfloat162float(hi));
    }
}

// ========== conv2 aggregate + residual + LN2 (4-edge groups, unroll 2) ======
__global__ __launch_bounds__(256) void conv2_ln(const __half* __restrict__ h2,
                                                const float* __restrict__ h2fw,
                                                const float* __restrict__ as2,
                                                const float* __restrict__ ad2,
                                                const int* __restrict__ off,
                                                const int* __restrict__ csr,
                                                const float* __restrict__ b2,
                                                const float* __restrict__ finalb,
                                                const float* __restrict__ g2,
                                                const float* __restrict__ bt2,
                                                float* __restrict__ out) {
    __shared__ float sal[8][CAP];
    int gwarp = (blockIdx.x * blockDim.x + threadIdx.x) >> 5;
    int lane = threadIdx.x & 31;
    if (gwarp >= NN) return;
    int v = gwarp;
    float* sm = sal[threadIdx.x >> 5];
    int s0 = off[v], d = off[v + 1] - s0;
    int grp = lane >> 3, ch8 = lane & 7;
    float adv = ad2[v], asv = as2[v];
    float eself = lrelu(asv + adv);
    float m = eself;
    float inv;
    bool fits = (d <= CAP);

    if (fits) {
        for (int j = lane; j < d; j += 32) {
            int s = csr[s0 + j];
            float e = lrelu(as2[s] + adv);
            sm[j] = e;
            m = fmaxf(m, e);
        }
        m = wredmax(m);
        float den = (lane == 0) ? __expf(eself - m) : 0.f;
        for (int j = lane; j < d; j += 32) {
            float e = __expf(sm[j] - m);
            sm[j] = e;
            den += e;
        }
        den = wredsum(den);
        inv = 1.f / (den + 1e-16f);
        __syncwarp();
    } else {
        for (int j = lane; j < d; j += 32) {
            int s = csr[s0 + j];
            m = fmaxf(m, lrelu(as2[s] + adv));
        }
        m = wredmax(m);
        float den = (lane == 0) ? __expf(eself - m) : 0.f;
        for (int j = lane; j < d; j += 32) {
            int s = csr[s0 + j];
            den += __expf(lrelu(as2[s] + adv) - m);
        }
        den = wredsum(den);
        inv = 1.f / (den + 1e-16f);
    }

    float2 acc[4];
    acc[0] = acc[1] = acc[2] = acc[3] = make_float2(0.f, 0.f);
    if (grp == 0) {
        uint4 r = ((const uint4*)(h2 + (long)v * 64))[ch8];
        fma8(acc, r, __expf(eself - m) * inv);
    }
    if (fits) {
        int j = grp;
        for (; j + 4 < d; j += 8) {
            int sA = csr[s0 + j], sB = csr[s0 + j + 4];
            uint4 rA = ((const uint4*)(h2 + (long)sA * 64))[ch8];
            uint4 rB = ((const uint4*)(h2 + (long)sB * 64))[ch8];
            fma8(acc, rA, sm[j] * inv);
            fma8(acc, rB, sm[j + 4] * inv);
        }
        for (; j < d; j += 4) {
            int s = csr[s0 + j];
            uint4 r = ((const uint4*)(h2 + (long)s * 64))[ch8];
            fma8(acc, r, sm[j] * inv);
        }
    } else {
        for (int j = grp; j < d; j += 4) {
            int s = csr[s0 + j];
            uint4 r = ((const uint4*)(h2 + (long)s * 64))[ch8];
            float a = __expf(lrelu(as2[s] + adv) - m) * inv;
            fma8(acc, r, a);
        }
    }
#pragma unroll
    for (int i = 0; i < 4; i++) {
        acc[i].x += __shfl_xor_sync(0xffffffffu, acc[i].x, 8);
        acc[i].x += __shfl_xor_sync(0xffffffffu, acc[i].x, 16);
        acc[i].y += __shfl_xor_sync(0xffffffffu, acc[i].y, 8);
        acc[i].y += __shfl_xor_sync(0xffffffffu, acc[i].y, 16);
    }
    float vals[8];
    float lsum = 0.f;
#pragma unroll
    for (int i = 0; i < 4; i++) {
        int c = ch8 * 8 + 2 * i;
        float r0 = acc[i].x + b2[c] + h2fw[(long)v * 128 + 64 + c] + finalb[c];
        float r1 = acc[i].y + b2[c + 1] + h2fw[(long)v * 128 + 64 + c + 1] + finalb[c + 1];
        vals[2 * i] = r0;
        vals[2 * i + 1] = r1;
        lsum += r0 + r1;
    }
    float sum = wredsum(lsum) * 0.25f;
    float mu = sum * (1.f / 64.f);
    float lvs = 0.f;
#pragma unroll
    for (int i = 0; i < 8; i++) {
        float dd = vals[i] - mu;
        lvs += dd * dd;
    }
    float vs = wredsum(lvs) * 0.25f;
    float istd = rsqrtf(vs * (1.f / 64.f) + 1e-5f);
    if (grp == 0) {
        float o[8];
#pragma unroll
        for (int i = 0; i < 8; i++) {
            int c = ch8 * 8 + i;
            o[i] = (vals[i] - mu) * istd * g2[c] + bt2[c];
        }
        float4* op = (float4*)(out + (long)v * 64 + ch8 * 8);
        op[0] = make_float4(o[0], o[1], o[2], o[3]);
        op[1] = make_float4(o[4], o[5], o[6], o[7]);
    }
}

__global__ void write_w(const float* __restrict__ ha, float* __restrict__ out) {
    if (threadIdx.x == 0) {
        float a0 = ha[0], a1 = ha[1];
        float mx = fmaxf(a0, a1);
        float e0 = __expf(a0 - mx), e1 = __expf(a1 - mx);
        float inv = 1.f / (e0 + e1);
        out[NN * 64 + 0] = e0 * inv;
        out[NN * 64 + 1] = e1 * inv;
    }
}

// ================= launch ===================================================
extern "C" void kernel_launch(void* const* d_in, const int* in_sizes, int n_in,
                              void* d_out, int out_size) {
    const float* x = (const float*)d_in[0];
    const int* ei = (const int*)d_in[1];
    const int* ei2 = (const int*)d_in[2];
    const float* W1 = (const float*)d_in[3];
    const float* att_src1 = (const float*)d_in[4];
    const float* att_dst1 = (const float*)d_in[5];
    const float* b1 = (const float*)d_in[6];
    const float* W2 = (const float*)d_in[7];
    const float* att_src2 = (const float*)d_in[8];
    const float* att_dst2 = (const float*)d_in[9];
    const float* b2 = (const float*)d_in[10];
    const float* ha = (const float*)d_in[11];
    const float* skipW = (const float*)d_in[12];
    const float* skipb = (const float*)d_in[13];
    const float* finalW = (const float*)d_in[14];
    const float* finalb = (const float*)d_in[15];
    const float* ln1g = (const float*)d_in[16];
    const float* ln1b = (const float*)d_in[17];
    const float* ln2g = (const float*)d_in[18];
    const float* ln2b = (const float*)d_in[19];
    float* out = (float*)d_out;

    GS* g = nullptr;
    cudaGetSymbolAddress((void**)&g, gs);

    static cudaStream_t sB = nullptr;
    static cudaEvent_t evFork = nullptr, evJoin = nullptr;
    if (!sB) {
        cudaStreamCreateWithFlags(&sB, cudaStreamNonBlocking);
        cudaEventCreateWithFlags(&evFork, cudaEventDisableTiming);
        cudaEventCreateWithFlags(&evJoin, cudaEventDisableTiming);
    }

    const int GSMEM = 2 * 40960;
    const int GSMEMF = 3 * 20480;
    cudaFuncSetAttribute(hmma_gemm, cudaFuncAttributeMaxDynamicSharedMemorySize, GSMEM);
    cudaFuncSetAttribute(hmma_gemm_f16, cudaFuncAttributeMaxDynamicSharedMemorySize, GSMEMF);

    const int TB = 256;
    int nb = (NN + TB - 1) / TB;
    int wb = (NN + 7) / 8;
    int eb2 = (2 * EE + TB - 1) / TB;

    // ---- fork: CSR build + pack_B2 on stream B ----
    cudaEventRecord(evFork, 0);
    cudaStreamWaitEvent(sB, evFork, 0);
    pack_B2<<<(128 * 256 + TB - 1) / TB, TB, 0, sB>>>(W2, finalW, g->B2h, g->B2l);
    zero_int<<<(2 * NN + TB - 1) / TB, TB, 0, sB>>>(g->deg0, 2 * NN);
    hist2<<<eb2, TB, 0, sB>>>(ei + EE, ei2 + EE, g->deg0, g->deg1);
    {
        dim3 gp(SBLK, 2);
        scan_part<<<gp, 256, 0, sB>>>(g->deg0, g->deg1, g->bsum);
        scan_mid<<<2, 256, 0, sB>>>(g->bsum, g->off0, g->off1);
        scan_emit<<<gp, 256, 0, sB>>>(g->deg0, g->deg1, g->bsum,
                                      g->off0, g->cur0, g->off1, g->cur1);
    }
    scatter2<<<eb2, TB, 0, sB>>>(ei, ei2, g->cur0, g->cur1, g->csr0, g->csr1);
    cudaEventRecord(evJoin, sB);

    // ---- main stream: operand prep + GEMM1 + logits ----
    split_x<<<(NN * 256 + TB - 1) / TB, TB>>>(x, g->xf, NN * 256);
    pack_B1f<<<(768 * 256 + TB - 1) / TB, TB>>>(W1, skipW, g->B1f);
    {
        dim3 grid(6, (NN + 127) / 128);
        hmma_gemm_f16<<<grid, 256, GSMEMF>>>(g->xf, g->B1f, g->h0f, g->h1f, g->skb, NN);
    }
    {
        dim3 grid((NN * 8 + TB - 1) / TB, 2);
        logits8_2<<<grid, TB>>>((const __half2*)g->h0f, (const __half2*)g->h1f,
                                att_src1, att_dst1, g->as0, g->ad0, g->as1, g->ad1);
    }

    // ---- join: aggregation needs CSR ----
    cudaStreamWaitEvent(0, evJoin, 0);
    {
        dim3 grid(wb, 2);
        gat_agg8_2<<<grid, TB>>>(g->h0f, g->h1f, g->as0, g->ad0, g->as1, g->ad1,
                                 g->off0, g->csr0, g->off1, g->csr1, g->agg0, g->agg1);
    }

    combine_ln<<<wb, TB>>>(g->agg0, g->agg1, g->skb, b1, skipb, ha, ln1g, ln1b,
                           g->fxh, g->fxl);

    // GEMM2 (bf16 split): first @ [W2 | final_W] -> h2fw (fp32) + h2f (fp16 mirror)
    {
        dim3 grid(1, (NN + 127) / 128);
        hmma_gemm<<<grid, 256, GSMEM>>>(g->fxh, g->fxl, g->B2h, g->B2l, g->h2fw, g->h2f,
                                        NN, 128);
    }

    logits1<<<nb, TB>>>((const __half2*)g->h2f, att_src2, att_dst2, g->as2, g->ad2);
    conv2_ln<<<wb, TB>>>(g->h2f, g->h2fw, g->as2, g->ad2, g->off0, g->csr0,
                         b2, finalb, ln2g, ln2b, out);
    write_w<<<1, 32>>>(ha, out);
}